// round 1
// baseline (speedup 1.0000x reference)
#include <cuda_runtime.h>
#include <math.h>
#include <float.h>

// Problem constants (fixed instance)
#define Bq 8
#define Nq 6
#define Mq 64
#define Vq 32000
#define Tq 8
#define NS (Nq + 1)          // 7 template slots
#define MV (Mq * Vq)
#define V4 (Vq / 4)          // 8000 float4 per row

// Scratch (no allocations allowed -> __device__ globals)
__device__ unsigned int g_bits[Bq * Mq];   // per (b,m): bit t set iff argmax_v(out[b,t,m,:]) == 0
__device__ int          g_rowmap[Bq * Mq]; // per (b,p): (t<<8)|mloc, or -1 for "stay zero"

// ---------------------------------------------------------------------------
// K1: one block per (b,m). Streams X[b,:,m,:] once.
//  - computes max_v of all 8 weighted rows + their v=0 values -> iszero bits
//  - writes the t=0 row to d_out (speculation: result[b,p,:] = out[b,0,p,:])
// ---------------------------------------------------------------------------
__global__ __launch_bounds__(256) void k_pass1(const float* __restrict__ X,
                                               const float* __restrict__ tmplt,
                                               const int*   __restrict__ spans,
                                               float*       __restrict__ out)
{
    const int bx  = blockIdx.x;
    const int b   = bx >> 6;
    const int m   = bx & 63;
    const int tid = threadIdx.x;

    __shared__ float w[Tq][NS];
    __shared__ float s_out0[Tq];
    __shared__ float s_wmax[8][Tq];

    if (tid < Tq * NS) {
        const int t = tid / NS, s = tid % NS;
        const float val = tmplt[b * Tq * NS + tid];
        w[t][s] = (s <= spans[b]) ? val : 0.0f;
    }
    __syncthreads();

    float tmax[Tq];
#pragma unroll
    for (int t = 0; t < Tq; t++) tmax[t] = -FLT_MAX;

    const size_t base = (size_t)b * Nq * MV + (size_t)m * Vq; // X[((b*N+n)*M+m)*V + v]
    float* orow = out + (size_t)(b * Mq + m) * Vq;

    for (int k = 0; k < 32; k++) {
        const int i4 = k * 256 + tid;
        if (i4 >= V4) break;
        const int v = i4 * 4;

        float4 x[Nq];
#pragma unroll
        for (int n = 0; n < Nq; n++)
            x[n] = *reinterpret_cast<const float4*>(X + base + (size_t)n * MV + v);

        float4 o0;
        float* o0p = reinterpret_cast<float*>(&o0);
#pragma unroll
        for (int j = 0; j < 4; j++) {
            float xv[Nq];
#pragma unroll
            for (int n = 0; n < Nq; n++) xv[n] = reinterpret_cast<const float*>(&x[n])[j];
            const bool special = (i4 == 0) && (j == 0);   // v == 0 element
#pragma unroll
            for (int t = 0; t < Tq; t++) {
                float o = 0.0f;
#pragma unroll
                for (int n = 0; n < Nq; n++) o = fmaf(w[t][n + 1], xv[n], o);
                if (special) {
                    if (m == 0) o += w[t][0];   // pad one-hot lands at (m=0, v=0)
                    s_out0[t] = o;
                }
                tmax[t] = fmaxf(tmax[t], o);
                if (t == 0) o0p[j] = o;
            }
        }
        *reinterpret_cast<float4*>(orow + v) = o0;  // speculative t=0 row
    }

    // reduce the 8 maxes: warp shuffle, then across the 8 warps
    const int lane = tid & 31, wid = tid >> 5;
#pragma unroll
    for (int t = 0; t < Tq; t++) {
        float val = tmax[t];
#pragma unroll
        for (int off = 16; off; off >>= 1)
            val = fmaxf(val, __shfl_xor_sync(0xffffffffu, val, off));
        if (lane == 0) s_wmax[wid][t] = val;
    }
    __syncthreads();

    if (tid < Tq) {
        const int t = tid;
        float mx = s_wmax[0][t];
#pragma unroll
        for (int wq = 1; wq < 8; wq++) mx = fmaxf(mx, s_wmax[wq][t]);
        // argmax==0  <=>  out[...,0] >= max over all v
        s_wmax[0][t] = (s_out0[t] >= mx) ? 1.0f : 0.0f;
    }
    __syncthreads();

    if (tid == 0) {
        unsigned mask = 0;
#pragma unroll
        for (int t = 0; t < Tq; t++)
            if (s_wmax[0][t] != 0.0f) mask |= (1u << t);
        g_bits[b * Mq + m] = mask;
    }
}

// ---------------------------------------------------------------------------
// K2: tiny serial scan, one thread per batch element.
// ---------------------------------------------------------------------------
__global__ void k_scan()
{
    const int b = threadIdx.x;
    if (b >= Bq) return;
    int idx = 0;
    for (int t = 0; t < Tq; t++) {
        int first = Mq;
        for (int m = 0; m < Mq; m++) {
            if ((g_bits[b * Mq + m] >> t) & 1u) { first = m; break; }
        }
        int len = min(first, Mq - idx);
        for (int p = idx; p < idx + len; p++)
            g_rowmap[b * Mq + p] = (t << 8) | (p - idx);
        idx += len;
    }
    for (int p = idx; p < Mq; p++) g_rowmap[b * Mq + p] = -1;
}

// ---------------------------------------------------------------------------
// K3: one block per (b,p). If speculation (t=0, mloc=p) was right, exit.
// Otherwise zero-fill or recompute the correct row.
// ---------------------------------------------------------------------------
__global__ __launch_bounds__(256) void k_fix(const float* __restrict__ X,
                                             const float* __restrict__ tmplt,
                                             const int*   __restrict__ spans,
                                             float*       __restrict__ out)
{
    const int bx = blockIdx.x;
    const int b  = bx >> 6;
    const int p  = bx & 63;
    const int rm = g_rowmap[b * Mq + p];
    if (rm == p) return;                       // t=0, mloc=p: speculative row is exact

    const int tid = threadIdx.x;
    float* orow = out + (size_t)(b * Mq + p) * Vq;

    if (rm < 0) {                              // never written -> zeros
        const float4 z = make_float4(0.f, 0.f, 0.f, 0.f);
        for (int i4 = tid; i4 < V4; i4 += 256)
            reinterpret_cast<float4*>(orow)[i4] = z;
        return;
    }

    const int t    = rm >> 8;
    const int mloc = rm & 255;

    __shared__ float w[NS];
    if (tid < NS) {
        const float val = tmplt[b * Tq * NS + t * NS + tid];
        w[tid] = (tid <= spans[b]) ? val : 0.0f;
    }
    __syncthreads();

    const size_t base = (size_t)b * Nq * MV + (size_t)mloc * Vq;
    for (int i4 = tid; i4 < V4; i4 += 256) {
        const int v = i4 * 4;
        float4 x[Nq];
#pragma unroll
        for (int n = 0; n < Nq; n++)
            x[n] = *reinterpret_cast<const float4*>(X + base + (size_t)n * MV + v);
        float4 o;
        float* op = reinterpret_cast<float*>(&o);
#pragma unroll
        for (int j = 0; j < 4; j++) {
            float acc = 0.0f;
#pragma unroll
            for (int n = 0; n < Nq; n++)
                acc = fmaf(w[n + 1], reinterpret_cast<const float*>(&x[n])[j], acc);
            op[j] = acc;
        }
        if (i4 == 0 && mloc == 0) op[0] += w[0];   // pad one-hot
        *reinterpret_cast<float4*>(orow + v) = o;
    }
}

extern "C" void kernel_launch(void* const* d_in, const int* in_sizes, int n_in,
                              void* d_out, int out_size)
{
    const float* X     = (const float*)d_in[0];  // [B,N,M,V] f32
    const float* tmplt = (const float*)d_in[1];  // [B,T,N+1] f32
    const int*   spans = (const int*)d_in[2];    // [B] i32
    float*       out   = (float*)d_out;          // [B,M,V] f32

    k_pass1<<<Bq * Mq, 256>>>(X, tmplt, spans, out);
    k_scan<<<1, 32>>>();
    k_fix<<<Bq * Mq, 256>>>(X, tmplt, spans, out);
}